// round 1
// baseline (speedup 1.0000x reference)
#include <cuda_runtime.h>
#include <math.h>

// Problem dims (fixed for this dataset; runtime-derived values asserted against these caps)
#define NATOMS 20000
#define NEDGES 250000
#define DE 512
#define DA 256
#define DR 16

#define INV_SQRT2 0.70710678118654752440f

// ---------------- scratch (device globals; no allocs allowed) ----------------
__device__ int   g_counts[NATOMS];
__device__ int   g_offsets[NATOMS + 1];
__device__ int   g_cursor[NATOMS];
__device__ int   g_sorted[NEDGES];
__device__ float g_xbig[(size_t)NATOMS * DE];   // aggregated edge features per atom [A, De]
__device__ float g_xa[(size_t)NATOMS * DA];     // current atom features [A, Da]
__device__ float g_ya[(size_t)NATOMS * DA];     // MLP intermediate [A, Da]

// ---------------- small helpers ----------------
__device__ __forceinline__ float silu(float x) {
    // x * sigmoid(x); __expf is MUFU-based, ~2ulp, far inside 1e-3 tolerance
    return x / (1.0f + __expf(-x));
}

// ---------------- counting sort of edges by atom ----------------
__global__ void zero_counts_kernel(int A) {
    int i = blockIdx.x * blockDim.x + threadIdx.x;
    if (i < A) g_counts[i] = 0;
}

__global__ void hist_kernel(const int* __restrict__ idx, int E) {
    int i = blockIdx.x * blockDim.x + threadIdx.x;
    if (i < E) atomicAdd(&g_counts[idx[i]], 1);
}

// single-block exclusive scan over counts -> offsets (+cursor copy)
__global__ void scan_kernel(int A, int E) {
    __shared__ int sums[1024];
    int tid = threadIdx.x;
    int per = (A + 1023) / 1024;
    int start = tid * per;
    int end = min(start + per, A);
    int s = 0;
    for (int i = start; i < end; i++) s += g_counts[i];
    sums[tid] = s;
    __syncthreads();
    // Hillis-Steele inclusive scan
    for (int off = 1; off < 1024; off <<= 1) {
        int v = 0;
        if (tid >= off) v = sums[tid - off];
        __syncthreads();
        sums[tid] += v;
        __syncthreads();
    }
    int run = (tid == 0) ? 0 : sums[tid - 1];
    for (int i = start; i < end; i++) {
        g_offsets[i] = run;
        g_cursor[i]  = run;
        run += g_counts[i];
    }
    if (tid == 0) g_offsets[A] = E;
}

__global__ void scatter_kernel(const int* __restrict__ idx, int E) {
    int i = blockIdx.x * blockDim.x + threadIdx.x;
    if (i < E) {
        int p = atomicAdd(&g_cursor[idx[i]], 1);
        g_sorted[p] = i;
    }
}

// ---------------- edge aggregation fused with rbf projection ----------------
// xbig[a, d] = sum_{e in atom a} m[e, d] * (sum_r basis_rad[e, r] * W_rbf[r, d])
// Persistent blocks; W_rbf columns held in registers (4 cols/thread, 128 threads = 512 cols).
__global__ void aggregate_kernel(const float* __restrict__ m,
                                 const float* __restrict__ br,
                                 const float* __restrict__ Wrbf,
                                 int A) {
    const int c0 = threadIdx.x * 4;  // this thread's 4 columns of De
    float4 w[DR];
#pragma unroll
    for (int r = 0; r < DR; r++)
        w[r] = *reinterpret_cast<const float4*>(Wrbf + (size_t)r * DE + c0);

    for (int a = blockIdx.x; a < A; a += gridDim.x) {
        float4 acc = make_float4(0.f, 0.f, 0.f, 0.f);
        int beg = g_offsets[a];
        int end = g_offsets[a + 1];
        for (int j = beg; j < end; j++) {
            int e = g_sorted[j];
            const float* bp = br + (size_t)e * DR;
            float4 t0 = *reinterpret_cast<const float4*>(bp);
            float4 t1 = *reinterpret_cast<const float4*>(bp + 4);
            float4 t2 = *reinterpret_cast<const float4*>(bp + 8);
            float4 t3 = *reinterpret_cast<const float4*>(bp + 12);
            float b[16] = {t0.x, t0.y, t0.z, t0.w, t1.x, t1.y, t1.z, t1.w,
                           t2.x, t2.y, t2.z, t2.w, t3.x, t3.y, t3.z, t3.w};
            float4 bs = make_float4(0.f, 0.f, 0.f, 0.f);
#pragma unroll
            for (int r = 0; r < DR; r++) {
                bs.x = fmaf(b[r], w[r].x, bs.x);
                bs.y = fmaf(b[r], w[r].y, bs.y);
                bs.z = fmaf(b[r], w[r].z, bs.z);
                bs.w = fmaf(b[r], w[r].w, bs.w);
            }
            float4 mv = *reinterpret_cast<const float4*>(m + (size_t)e * DE + c0);
            acc.x = fmaf(mv.x, bs.x, acc.x);
            acc.y = fmaf(mv.y, bs.y, acc.y);
            acc.z = fmaf(mv.z, bs.z, acc.z);
            acc.w = fmaf(mv.w, bs.w, acc.w);
        }
        *reinterpret_cast<float4*>(g_xbig + (size_t)a * DE + c0) = acc;
    }
}

// ---------------- tiled fp32 GEMM with fused silu (+optional residual) ----------------
// out[M,N] = silu(Ain[M,K] @ W[K,N])                      (mode 0)
// out[M,N] = (res[M,N] + silu(Ain @ W)) * INV_SQRT2       (mode 1; in-place res==out ok)
#define BM 128
#define BN 128
#define BK 16
#define TM 8
#define TN 8

__global__ __launch_bounds__(256, 2)
void gemm_silu_kernel(const float* __restrict__ Ain, const float* __restrict__ W,
                      const float* __restrict__ res, float* __restrict__ out,
                      int M, int K, int N, int mode) {
    __shared__ __align__(16) float As[BK][BM];
    __shared__ __align__(16) float Bs[BK][BN];

    const int bm = blockIdx.x * BM;
    const int bn = blockIdx.y * BN;
    const int tid = threadIdx.x;
    const int tr = tid / 16;   // 0..15
    const int tc = tid % 16;   // 0..15

    float acc[TM][TN];
#pragma unroll
    for (int i = 0; i < TM; i++)
#pragma unroll
        for (int j = 0; j < TN; j++) acc[i][j] = 0.f;

    for (int k0 = 0; k0 < K; k0 += BK) {
        // load A tile (BM x BK), store transposed As[k][row]
#pragma unroll
        for (int i = 0; i < 2; i++) {
            int r = tid / 4 + i * 64;       // 0..127
            int c = (tid % 4) * 4;          // 0,4,8,12
            float4 v = make_float4(0.f, 0.f, 0.f, 0.f);
            if (bm + r < M)
                v = *reinterpret_cast<const float4*>(Ain + (size_t)(bm + r) * K + k0 + c);
            As[c + 0][r] = v.x;
            As[c + 1][r] = v.y;
            As[c + 2][r] = v.z;
            As[c + 3][r] = v.w;
        }
        // load B tile (BK x BN)
#pragma unroll
        for (int i = 0; i < 2; i++) {
            int r = tid / 32 + i * 8;       // 0..15
            int c = (tid % 32) * 4;         // 0..124
            *reinterpret_cast<float4*>(&Bs[r][c]) =
                *reinterpret_cast<const float4*>(W + (size_t)(k0 + r) * N + bn + c);
        }
        __syncthreads();

#pragma unroll
        for (int k = 0; k < BK; k++) {
            float4 a0 = *reinterpret_cast<float4*>(&As[k][tr * TM]);
            float4 a1 = *reinterpret_cast<float4*>(&As[k][tr * TM + 4]);
            float4 b0 = *reinterpret_cast<float4*>(&Bs[k][tc * TN]);
            float4 b1 = *reinterpret_cast<float4*>(&Bs[k][tc * TN + 4]);
            float af[TM] = {a0.x, a0.y, a0.z, a0.w, a1.x, a1.y, a1.z, a1.w};
            float bf[TN] = {b0.x, b0.y, b0.z, b0.w, b1.x, b1.y, b1.z, b1.w};
#pragma unroll
            for (int i = 0; i < TM; i++)
#pragma unroll
                for (int j = 0; j < TN; j++)
                    acc[i][j] = fmaf(af[i], bf[j], acc[i][j]);
        }
        __syncthreads();
    }

    // epilogue
#pragma unroll
    for (int i = 0; i < TM; i++) {
        int row = bm + tr * TM + i;
        if (row >= M) continue;
#pragma unroll
        for (int j = 0; j < TN; j++) {
            int col = bn + tc * TN + j;
            float s = silu(acc[i][j]);
            if (mode == 1) s = (res[(size_t)row * N + col] + s) * INV_SQRT2;
            out[(size_t)row * N + col] = s;
        }
    }
}

// ---------------- launch ----------------
extern "C" void kernel_launch(void* const* d_in, const int* in_sizes, int n_in,
                              void* d_out, int out_size) {
    // inputs: 0:h (unused), 1:m, 2:basis_rad, 3:idx_atom, 4:W_rbf, 5:W_in, 6:res_W1, 7:res_W2
    const float* m    = (const float*)d_in[1];
    const float* br   = (const float*)d_in[2];
    const int*   idx  = (const int*)d_in[3];
    const float* Wrbf = (const float*)d_in[4];
    const float* Win  = (const float*)d_in[5];
    const float* W1   = (const float*)d_in[6];
    const float* W2   = (const float*)d_in[7];
    float* out = (float*)d_out;

    int A  = in_sizes[0] / DA;           // 20000
    int E  = in_sizes[1] / DE;           // 250000
    int nh = in_sizes[6] / (DA * DA);    // 3
    if (A > NATOMS) A = NATOMS;
    if (E > NEDGES) E = NEDGES;

    float *xbig, *xa, *ya;
    cudaGetSymbolAddress((void**)&xbig, g_xbig);
    cudaGetSymbolAddress((void**)&xa, g_xa);
    cudaGetSymbolAddress((void**)&ya, g_ya);

    // counting sort of edges by atom
    zero_counts_kernel<<<(A + 255) / 256, 256>>>(A);
    hist_kernel<<<(E + 255) / 256, 256>>>(idx, E);
    scan_kernel<<<1, 1024>>>(A, E);
    scatter_kernel<<<(E + 255) / 256, 256>>>(idx, E);

    // edge aggregation fused with rbf projection
    aggregate_kernel<<<1184, 128>>>(m, br, Wrbf, A);

    dim3 grid1((A + BM - 1) / BM, DA / BN);
    // x = silu(xbig @ W_in)
    gemm_silu_kernel<<<grid1, 256>>>(xbig, Win, nullptr, xa, A, DE, DA, 0);

    // residual layers
    for (int i = 0; i < nh; i++) {
        const float* w1 = W1 + (size_t)i * DA * DA;
        const float* w2 = W2 + (size_t)i * DA * DA;
        gemm_silu_kernel<<<grid1, 256>>>(xa, w1, nullptr, ya, A, DA, DA, 0);
        float* dst = (i == nh - 1) ? out : xa;
        gemm_silu_kernel<<<grid1, 256>>>(ya, w2, xa, dst, A, DA, DA, 1);
    }
}

// round 3
// speedup vs baseline: 1.6957x; 1.6957x over previous
#include <cuda_runtime.h>
#include <cstdint>
#include <math.h>

// Problem dims (fixed for this dataset)
#define NATOMS 20000
#define NEDGES 250000
#define DE 512
#define DA 256
#define DR 16

#define INV_SQRT2 0.70710678118654752440f

// ---------------- scratch (device globals; no allocs allowed) ----------------
__device__ int   g_counts[NATOMS];
__device__ int   g_offsets[NATOMS + 1];
__device__ int   g_cursor[NATOMS];
__device__ int   g_sorted[NEDGES];
__device__ float g_xbig[(size_t)NATOMS * DE];   // aggregated edge features [A, De] (tf32-rounded)
__device__ float g_xa[(size_t)NATOMS * DA];     // atom features [A, Da]
__device__ float g_ya[(size_t)NATOMS * DA];     // MLP intermediate [A, Da]
// transposed+tf32-rounded weights: W_in^T [256,512] then 3x(W1^T,W2^T) [256,256]
__device__ float g_wt[DA * DE + 6 * DA * DA];

// ---------------- helpers ----------------
__device__ __forceinline__ uint32_t smem_u32(const void* p) {
    uint32_t a;
    asm("{ .reg .u64 t; cvta.to.shared.u64 t, %1; cvt.u32.u64 %0, t; }" : "=r"(a) : "l"(p));
    return a;
}
__device__ __forceinline__ float tf32_rna(float x) {
    float y;
    asm("cvt.rna.tf32.f32 %0, %1;" : "=f"(y) : "f"(x));
    return y;
}
__device__ __forceinline__ float silu(float x) { return x / (1.0f + __expf(-x)); }

__device__ __forceinline__ void cp_async16(uint32_t dst, const void* src, int pred) {
    asm volatile("cp.async.cg.shared.global [%0], [%1], 16, %2;"
                 :: "r"(dst), "l"(src), "r"(pred ? 16 : 0) : "memory");
}
__device__ __forceinline__ void cp_commit() {
    asm volatile("cp.async.commit_group;" ::: "memory");
}
__device__ __forceinline__ void cp_wait0() {
    asm volatile("cp.async.wait_group 0;" ::: "memory");
}

// ---------------- counting sort of edges by atom ----------------
__global__ void zero_counts_kernel(int A) {
    int i = blockIdx.x * blockDim.x + threadIdx.x;
    if (i < A) g_counts[i] = 0;
}
__global__ void hist_kernel(const int* __restrict__ idx, int E) {
    int i = blockIdx.x * blockDim.x + threadIdx.x;
    if (i < E) atomicAdd(&g_counts[idx[i]], 1);
}
__global__ void scan_kernel(int A, int E) {
    __shared__ int sums[1024];
    int tid = threadIdx.x;
    int per = (A + 1023) / 1024;
    int start = tid * per;
    int end = min(start + per, A);
    int s = 0;
    for (int i = start; i < end; i++) s += g_counts[i];
    sums[tid] = s;
    __syncthreads();
    for (int off = 1; off < 1024; off <<= 1) {
        int v = 0;
        if (tid >= off) v = sums[tid - off];
        __syncthreads();
        sums[tid] += v;
        __syncthreads();
    }
    int run = (tid == 0) ? 0 : sums[tid - 1];
    for (int i = start; i < end; i++) {
        g_offsets[i] = run;
        g_cursor[i]  = run;
        run += g_counts[i];
    }
    if (tid == 0) g_offsets[A] = E;
}
__global__ void scatter_kernel(const int* __restrict__ idx, int E) {
    int i = blockIdx.x * blockDim.x + threadIdx.x;
    if (i < E) {
        int p = atomicAdd(&g_cursor[idx[i]], 1);
        g_sorted[p] = i;
    }
}

// ---------------- edge aggregation fused with rbf projection ----------------
// xbig[a, d] = rna( sum_{e in atom a} m[e,d] * (sum_r basis_rad[e,r] * W_rbf[r,d]) )
__global__ void aggregate_kernel(const float* __restrict__ m,
                                 const float* __restrict__ br,
                                 const float* __restrict__ Wrbf,
                                 int A) {
    const int c0 = threadIdx.x * 4;
    float4 w[DR];
#pragma unroll
    for (int r = 0; r < DR; r++)
        w[r] = *reinterpret_cast<const float4*>(Wrbf + (size_t)r * DE + c0);

    for (int a = blockIdx.x; a < A; a += gridDim.x) {
        float4 acc = make_float4(0.f, 0.f, 0.f, 0.f);
        int beg = g_offsets[a];
        int end = g_offsets[a + 1];
        for (int j = beg; j < end; j++) {
            int e = g_sorted[j];
            const float* bp = br + (size_t)e * DR;
            float4 t0 = *reinterpret_cast<const float4*>(bp);
            float4 t1 = *reinterpret_cast<const float4*>(bp + 4);
            float4 t2 = *reinterpret_cast<const float4*>(bp + 8);
            float4 t3 = *reinterpret_cast<const float4*>(bp + 12);
            float b[16] = {t0.x, t0.y, t0.z, t0.w, t1.x, t1.y, t1.z, t1.w,
                           t2.x, t2.y, t2.z, t2.w, t3.x, t3.y, t3.z, t3.w};
            float4 bs = make_float4(0.f, 0.f, 0.f, 0.f);
#pragma unroll
            for (int r = 0; r < DR; r++) {
                bs.x = fmaf(b[r], w[r].x, bs.x);
                bs.y = fmaf(b[r], w[r].y, bs.y);
                bs.z = fmaf(b[r], w[r].z, bs.z);
                bs.w = fmaf(b[r], w[r].w, bs.w);
            }
            float4 mv = *reinterpret_cast<const float4*>(m + (size_t)e * DE + c0);
            acc.x = fmaf(mv.x, bs.x, acc.x);
            acc.y = fmaf(mv.y, bs.y, acc.y);
            acc.z = fmaf(mv.z, bs.z, acc.z);
            acc.w = fmaf(mv.w, bs.w, acc.w);
        }
        // tf32-round so downstream mma truncation is exact
        acc.x = tf32_rna(acc.x); acc.y = tf32_rna(acc.y);
        acc.z = tf32_rna(acc.z); acc.w = tf32_rna(acc.w);
        *reinterpret_cast<float4*>(g_xbig + (size_t)a * DE + c0) = acc;
    }
}

// ---------------- W transpose + tf32 rounding: out[n*K+k] = rna(in[k*N+n]) ----------------
__global__ void transpose_rna_kernel(const float* __restrict__ in, float* __restrict__ out,
                                     int K, int N) {
    int i = blockIdx.x * blockDim.x + threadIdx.x;
    if (i < K * N) {
        int k = i / N, n = i % N;
        out[(size_t)n * K + k] = tf32_rna(in[i]);
    }
}

// ---------------- mma.sync tf32 GEMM, tile 128x128, fused silu/residual ----------------
// mode 0: out = silu(A @ W^T)      mode 1: out = (res + silu(A @ W^T)) * INV_SQRT2
// Wt: [N, K] row-major (K-major rows), pre-rounded to tf32. A values pre-rounded to tf32.
// round_out: additionally rna-round the stored result (when it feeds another GEMM).
#define BK 32
#define LDS_K 36    // padded row stride in floats (conflict-free: 36 mod 32 = 4)
#define TILE_FLOATS (128 * LDS_K)
#define GEMM_SMEM (4 * TILE_FLOATS * 4)   // A0,A1,B0,B1 = 73728 B

__global__ __launch_bounds__(256, 2)
void gemm_mma_kernel(const float* __restrict__ Ain, const float* __restrict__ Wt,
                     const float* __restrict__ res, float* __restrict__ out,
                     int M, int K, int mode, int round_out) {
    extern __shared__ float smem[];
    float* sA[2] = {smem, smem + TILE_FLOATS};
    float* sB[2] = {smem + 2 * TILE_FLOATS, smem + 3 * TILE_FLOATS};
    const uint32_t sbase = smem_u32(smem);

    const int tid = threadIdx.x;
    const int lane = tid & 31;
    const int wid = tid >> 5;
    const int warp_m = wid & 3;       // 0..3 -> 32-row slice
    const int warp_n = wid >> 2;      // 0..1 -> 64-col slice
    const int bm = blockIdx.x * 128;
    const int bn = blockIdx.y * 128;

    // loader indices: thread t loads row t/2, 16 consecutive floats (4x float4)
    const int ld_row = tid >> 1;
    const int ld_col = (tid & 1) * 16;
    const bool a_valid = (bm + ld_row) < M;
    const float* gA = Ain + (size_t)(bm + ld_row) * K + ld_col;
    const float* gB = Wt + (size_t)(bn + ld_row) * K + ld_col;
    const uint32_t sA_dst[2] = {sbase + (0 * TILE_FLOATS + ld_row * LDS_K + ld_col) * 4,
                                sbase + (1 * TILE_FLOATS + ld_row * LDS_K + ld_col) * 4};
    const uint32_t sB_dst[2] = {sbase + (2 * TILE_FLOATS + ld_row * LDS_K + ld_col) * 4,
                                sbase + (3 * TILE_FLOATS + ld_row * LDS_K + ld_col) * 4};

    auto prefetch = [&](int kt, int buf) {
        int k0 = kt * BK;
#pragma unroll
        for (int j = 0; j < 4; j++)
            cp_async16(sA_dst[buf] + j * 16, gA + k0 + j * 4, a_valid);
#pragma unroll
        for (int j = 0; j < 4; j++)
            cp_async16(sB_dst[buf] + j * 16, gB + k0 + j * 4, 1);
        cp_commit();
    };

    float acc[2][8][4];
#pragma unroll
    for (int mt = 0; mt < 2; mt++)
#pragma unroll
        for (int nt = 0; nt < 8; nt++)
#pragma unroll
            for (int v = 0; v < 4; v++) acc[mt][nt][v] = 0.f;

    const int nk = K / BK;
    const int r = lane >> 2;   // group id
    const int c = lane & 3;    // thread in group

    prefetch(0, 0);
    int buf = 0;
    for (int kt = 0; kt < nk; kt++) {
        cp_wait0();
        __syncthreads();
        if (kt + 1 < nk) prefetch(kt + 1, buf ^ 1);

        const float* wA = sA[buf] + (warp_m * 32) * LDS_K;
        const float* wB = sB[buf] + (warp_n * 64) * LDS_K;
#pragma unroll
        for (int ks = 0; ks < 4; ks++) {
            const int kk = ks * 8;
            uint32_t a[2][4];
#pragma unroll
            for (int mt = 0; mt < 2; mt++) {
                const float* p = wA + (mt * 16 + r) * LDS_K + kk + c;
                a[mt][0] = __float_as_uint(p[0]);
                a[mt][1] = __float_as_uint(p[8 * LDS_K]);
                a[mt][2] = __float_as_uint(p[4]);
                a[mt][3] = __float_as_uint(p[8 * LDS_K + 4]);
            }
            uint32_t b[8][2];
#pragma unroll
            for (int nt = 0; nt < 8; nt++) {
                const float* p = wB + (nt * 8 + r) * LDS_K + kk + c;
                b[nt][0] = __float_as_uint(p[0]);
                b[nt][1] = __float_as_uint(p[4]);
            }
#pragma unroll
            for (int mt = 0; mt < 2; mt++)
#pragma unroll
                for (int nt = 0; nt < 8; nt++) {
                    float* d = acc[mt][nt];
                    asm volatile(
                        "mma.sync.aligned.m16n8k8.row.col.f32.tf32.tf32.f32 "
                        "{%0,%1,%2,%3}, {%4,%5,%6,%7}, {%8,%9}, {%0,%1,%2,%3};"
                        : "+f"(d[0]), "+f"(d[1]), "+f"(d[2]), "+f"(d[3])
                        : "r"(a[mt][0]), "r"(a[mt][1]), "r"(a[mt][2]), "r"(a[mt][3]),
                          "r"(b[nt][0]), "r"(b[nt][1]));
                }
        }
        __syncthreads();
        buf ^= 1;
    }

    // ---- epilogue: c0,c1 at (row, col..col+1); c2,c3 at (row+8, ...) ----
#pragma unroll
    for (int mt = 0; mt < 2; mt++) {
        int row0 = bm + warp_m * 32 + mt * 16 + r;
#pragma unroll
        for (int half = 0; half < 2; half++) {
            int row = row0 + half * 8;
            if (row >= M) continue;
            float* op = out + (size_t)row * DA;
            const float* rp = (mode == 1) ? res + (size_t)row * DA : nullptr;
#pragma unroll
            for (int nt = 0; nt < 8; nt++) {
                int col = bn + warp_n * 64 + nt * 8 + c * 2;
                float v0 = silu(acc[mt][nt][half * 2 + 0]);
                float v1 = silu(acc[mt][nt][half * 2 + 1]);
                if (mode == 1) {
                    float2 rv = *reinterpret_cast<const float2*>(rp + col);
                    v0 = (rv.x + v0) * INV_SQRT2;
                    v1 = (rv.y + v1) * INV_SQRT2;
                }
                if (round_out) { v0 = tf32_rna(v0); v1 = tf32_rna(v1); }
                *reinterpret_cast<float2*>(op + col) = make_float2(v0, v1);
            }
        }
    }
}

// ---------------- launch ----------------
extern "C" void kernel_launch(void* const* d_in, const int* in_sizes, int n_in,
                              void* d_out, int out_size) {
    // inputs: 0:h (unused), 1:m, 2:basis_rad, 3:idx_atom, 4:W_rbf, 5:W_in, 6:res_W1, 7:res_W2
    const float* m    = (const float*)d_in[1];
    const float* br   = (const float*)d_in[2];
    const int*   idx  = (const int*)d_in[3];
    const float* Wrbf = (const float*)d_in[4];
    const float* Win  = (const float*)d_in[5];
    const float* W1   = (const float*)d_in[6];
    const float* W2   = (const float*)d_in[7];
    float* out = (float*)d_out;

    int A  = in_sizes[0] / DA;           // 20000
    int E  = in_sizes[1] / DE;           // 250000
    int nh = in_sizes[6] / (DA * DA);    // 3
    if (A > NATOMS) A = NATOMS;
    if (E > NEDGES) E = NEDGES;

    float *xbig, *xa, *ya, *wt;
    cudaGetSymbolAddress((void**)&xbig, g_xbig);
    cudaGetSymbolAddress((void**)&xa, g_xa);
    cudaGetSymbolAddress((void**)&ya, g_ya);
    cudaGetSymbolAddress((void**)&wt, g_wt);

    static bool attr_set = false;
    if (!attr_set) {
        cudaFuncSetAttribute(gemm_mma_kernel,
                             cudaFuncAttributeMaxDynamicSharedMemorySize, GEMM_SMEM);
        attr_set = true;
    }

    // counting sort of edges by atom
    zero_counts_kernel<<<(A + 255) / 256, 256>>>(A);
    hist_kernel<<<(E + 255) / 256, 256>>>(idx, E);
    scan_kernel<<<1, 1024>>>(A, E);
    scatter_kernel<<<(E + 255) / 256, 256>>>(idx, E);

    // edge aggregation fused with rbf projection
    aggregate_kernel<<<1184, 128>>>(m, br, Wrbf, A);

    // transpose + tf32-round all weight matrices
    float* wt0 = wt;                       // [256, 512]
    transpose_rna_kernel<<<(DE * DA + 255) / 256, 256>>>(Win, wt0, DE, DA);
    for (int i = 0; i < nh; i++) {
        float* w1t = wt + DA * DE + (size_t)(2 * i) * DA * DA;
        float* w2t = wt + DA * DE + (size_t)(2 * i + 1) * DA * DA;
        transpose_rna_kernel<<<(DA * DA + 255) / 256, 256>>>(W1 + (size_t)i * DA * DA, w1t, DA, DA);
        transpose_rna_kernel<<<(DA * DA + 255) / 256, 256>>>(W2 + (size_t)i * DA * DA, w2t, DA, DA);
    }

    dim3 grid((A + 127) / 128, DA / 128);
    // x = silu(xbig @ W_in)
    gemm_mma_kernel<<<grid, 256, GEMM_SMEM>>>(xbig, wt0, nullptr, xa, A, DE, 0, 1);

    // residual layers
    for (int i = 0; i < nh; i++) {
        float* w1t = wt + DA * DE + (size_t)(2 * i) * DA * DA;
        float* w2t = wt + DA * DE + (size_t)(2 * i + 1) * DA * DA;
        gemm_mma_kernel<<<grid, 256, GEMM_SMEM>>>(xa, w1t, nullptr, ya, A, DA, 0, 1);
        float* dst = (i == nh - 1) ? out : xa;
        int ro = (i == nh - 1) ? 0 : 1;
        gemm_mma_kernel<<<grid, 256, GEMM_SMEM>>>(ya, w2t, xa, dst, A, DA, 1, ro);
    }
}

// round 4
// speedup vs baseline: 1.7724x; 1.0453x over previous
#include <cuda_runtime.h>
#include <cstdint>
#include <math.h>

// Problem dims (fixed for this dataset)
#define NATOMS 20000
#define NEDGES 250000
#define DE 512
#define DA 256
#define DR 16

#define INV_SQRT2 0.70710678118654752440f

// K-permutation within each 32-element block: k' = (k%4)*8 + (k/4)%8
__host__ __device__ __forceinline__ int kperm(int k) {
    return (k & ~31) | ((k & 3) * 8) | ((k & 31) >> 2);
}

// ---------------- scratch (device globals; no allocs allowed) ----------------
__device__ int   g_counts[NATOMS];          // zero at load; scan re-zeroes each pass
__device__ int   g_offsets[NATOMS + 1];
__device__ int   g_cursor[NATOMS];
__device__ int   g_sorted[NEDGES];
__device__ float g_xbig[(size_t)NATOMS * DE];   // aggregated edge features [A, De] (tf32, k-permuted)
__device__ float g_xa[(size_t)NATOMS * DA];     // atom features (tf32, k-permuted)
__device__ float g_ya[(size_t)NATOMS * DA];     // MLP intermediate (tf32, k-permuted)
// transposed+tf32-rounded+k-permuted weights: W_in^T [256,512] then 3x(W1^T,W2^T) [256,256]
__device__ float g_wt[DA * DE + 6 * DA * DA];

// ---------------- helpers ----------------
__device__ __forceinline__ uint32_t smem_u32(const void* p) {
    uint32_t a;
    asm("{ .reg .u64 t; cvta.to.shared.u64 t, %1; cvt.u32.u64 %0, t; }" : "=r"(a) : "l"(p));
    return a;
}
__device__ __forceinline__ float tf32_rna(float x) {
    float y;
    asm("cvt.rna.tf32.f32 %0, %1;" : "=f"(y) : "f"(x));
    return y;
}
__device__ __forceinline__ float silu(float x) { return x / (1.0f + __expf(-x)); }

__device__ __forceinline__ void cp_async16(uint32_t dst, const void* src, int pred) {
    asm volatile("cp.async.cg.shared.global [%0], [%1], 16, %2;"
                 :: "r"(dst), "l"(src), "r"(pred ? 16 : 0) : "memory");
}
__device__ __forceinline__ void cp_commit() {
    asm volatile("cp.async.commit_group;" ::: "memory");
}
__device__ __forceinline__ void cp_wait0() {
    asm volatile("cp.async.wait_group 0;" ::: "memory");
}

// ---------------- counting sort of edges by atom ----------------
__global__ void hist_kernel(const int* __restrict__ idx, int E) {
    int i = blockIdx.x * blockDim.x + threadIdx.x;
    if (i < E) atomicAdd(&g_counts[idx[i]], 1);
}
// single-block scan; also re-zeroes g_counts so the next graph replay starts clean
__global__ void scan_kernel(int A, int E) {
    __shared__ int sums[1024];
    int tid = threadIdx.x;
    int per = (A + 1023) / 1024;
    int start = tid * per;
    int end = min(start + per, A);
    int s = 0;
    for (int i = start; i < end; i++) s += g_counts[i];
    sums[tid] = s;
    __syncthreads();
    for (int off = 1; off < 1024; off <<= 1) {
        int v = 0;
        if (tid >= off) v = sums[tid - off];
        __syncthreads();
        sums[tid] += v;
        __syncthreads();
    }
    int run = (tid == 0) ? 0 : sums[tid - 1];
    for (int i = start; i < end; i++) {
        g_offsets[i] = run;
        g_cursor[i]  = run;
        run += g_counts[i];
        g_counts[i] = 0;
    }
    if (tid == 0) g_offsets[A] = E;
}
__global__ void scatter_kernel(const int* __restrict__ idx, int E) {
    int i = blockIdx.x * blockDim.x + threadIdx.x;
    if (i < E) {
        int p = atomicAdd(&g_cursor[idx[i]], 1);
        g_sorted[p] = i;
    }
}

// ---------------- edge aggregation fused with rbf projection (1-ahead pipelined) ----------------
// xbig[a, perm(d)] = rna( sum_{e in atom a} m[e,d] * (sum_r basis_rad[e,r] * W_rbf[r,d]) )
__global__ void aggregate_kernel(const float* __restrict__ m,
                                 const float* __restrict__ br,
                                 const float* __restrict__ Wrbf,
                                 int A) {
    const int c0 = threadIdx.x * 4;
    float4 w[DR];
#pragma unroll
    for (int r = 0; r < DR; r++)
        w[r] = *reinterpret_cast<const float4*>(Wrbf + (size_t)r * DE + c0);

    // permuted store positions for this thread's 4 columns (k = c0..c0+3)
    const int pbase = (threadIdx.x >> 3) * 32 + (threadIdx.x & 7);

    for (int a = blockIdx.x; a < A; a += gridDim.x) {
        float4 acc = make_float4(0.f, 0.f, 0.f, 0.f);
        int beg = g_offsets[a];
        int end = g_offsets[a + 1];
        if (beg < end) {
            int e = g_sorted[beg];
            float4 mv = *reinterpret_cast<const float4*>(m + (size_t)e * DE + c0);
            const float* bp = br + (size_t)e * DR;
            float4 t0 = *reinterpret_cast<const float4*>(bp);
            float4 t1 = *reinterpret_cast<const float4*>(bp + 4);
            float4 t2 = *reinterpret_cast<const float4*>(bp + 8);
            float4 t3 = *reinterpret_cast<const float4*>(bp + 12);
            for (int j = beg; j < end; j++) {
                // prefetch next edge's data while computing current
                int e_n = (j + 1 < end) ? g_sorted[j + 1] : e;
                float4 mv_n = *reinterpret_cast<const float4*>(m + (size_t)e_n * DE + c0);
                const float* bpn = br + (size_t)e_n * DR;
                float4 n0 = *reinterpret_cast<const float4*>(bpn);
                float4 n1 = *reinterpret_cast<const float4*>(bpn + 4);
                float4 n2 = *reinterpret_cast<const float4*>(bpn + 8);
                float4 n3 = *reinterpret_cast<const float4*>(bpn + 12);

                float b[16] = {t0.x, t0.y, t0.z, t0.w, t1.x, t1.y, t1.z, t1.w,
                               t2.x, t2.y, t2.z, t2.w, t3.x, t3.y, t3.z, t3.w};
                float4 bs = make_float4(0.f, 0.f, 0.f, 0.f);
#pragma unroll
                for (int r = 0; r < DR; r++) {
                    bs.x = fmaf(b[r], w[r].x, bs.x);
                    bs.y = fmaf(b[r], w[r].y, bs.y);
                    bs.z = fmaf(b[r], w[r].z, bs.z);
                    bs.w = fmaf(b[r], w[r].w, bs.w);
                }
                acc.x = fmaf(mv.x, bs.x, acc.x);
                acc.y = fmaf(mv.y, bs.y, acc.y);
                acc.z = fmaf(mv.z, bs.z, acc.z);
                acc.w = fmaf(mv.w, bs.w, acc.w);

                mv = mv_n; t0 = n0; t1 = n1; t2 = n2; t3 = n3;
            }
        }
        // tf32-round + k-permuted store (feeds GEMM1 A operand)
        float* op = g_xbig + (size_t)a * DE + pbase;
        op[0]  = tf32_rna(acc.x);
        op[8]  = tf32_rna(acc.y);
        op[16] = tf32_rna(acc.z);
        op[24] = tf32_rna(acc.w);
    }
}

// ---------------- all-weights transpose + tf32 round + k-permute (single launch) ----------------
// wt layout: [0, DA*DE): W_in^T ; then per layer i: W1^T, W2^T at DA*DE + (2i / 2i+1)*DA*DA
__global__ void transpose_all_kernel(const float* __restrict__ Win,
                                     const float* __restrict__ W1,
                                     const float* __restrict__ W2,
                                     float* __restrict__ wt, int nh) {
    int total = DE * DA + 2 * nh * DA * DA;
    for (int i = blockIdx.x * blockDim.x + threadIdx.x; i < total;
         i += gridDim.x * blockDim.x) {
        const float* src;
        float* dst;
        int K, rem;
        if (i < DE * DA) {
            src = Win; dst = wt; K = DE; rem = i;
        } else {
            int j = i - DE * DA;
            int t = j / (DA * DA);
            rem = j % (DA * DA);
            src = ((t & 1) == 0 ? W1 : W2) + (size_t)(t >> 1) * DA * DA;
            dst = wt + DE * DA + (size_t)t * DA * DA;
            K = DA;
        }
        int k = rem / DA, n = rem % DA;
        dst[(size_t)n * K + kperm(k)] = tf32_rna(src[rem]);
    }
}

// ---------------- mma.sync tf32 GEMM, tile 64x128, k-permuted operands ----------------
// mode 0: out = silu(A @ W^T)      mode 1: out = (res + silu(A @ W^T)) * INV_SQRT2
// perm_out=1: store with k-permuted + rna-rounded columns (feeds next GEMM); 0: plain fp32.
#define BK 32
#define LDS_K 36
#define A_FLOATS (64 * LDS_K)
#define B_FLOATS (128 * LDS_K)
#define BUF_FLOATS (A_FLOATS + B_FLOATS)
#define GEMM_SMEM (2 * BUF_FLOATS * 4)   // 55296 B

__global__ __launch_bounds__(128, 3)
void gemm_mma_kernel(const float* __restrict__ Ain, const float* __restrict__ Wt,
                     const float* __restrict__ res, float* __restrict__ out,
                     int M, int K, int mode, int perm_out) {
    extern __shared__ float smem[];
    float* sA[2] = {smem, smem + BUF_FLOATS};
    float* sB[2] = {smem + A_FLOATS, smem + BUF_FLOATS + A_FLOATS};
    const uint32_t sbase = smem_u32(smem);

    const int tid = threadIdx.x;
    const int lane = tid & 31;
    const int wid = tid >> 5;
    const int warp_m = wid & 1;       // 2 x 32 rows
    const int warp_n = wid >> 1;      // 2 x 64 cols
    const int bm = blockIdx.x * 64;
    const int bn = blockIdx.y * 128;
    const int r = lane >> 2;
    const int c = lane & 3;

    // A loader: thread t -> row t/2, 16 floats at (t&1)*16, 4 cp.async
    const int a_row = tid >> 1;
    const int a_col = (tid & 1) * 16;
    const bool a_valid = (bm + a_row) < M;
    const float* gA = Ain + (size_t)(bm + a_row) * K + a_col;
    // B loader: thread t -> row t, 32 floats, 8 cp.async
    const float* gB = Wt + (size_t)(bn + tid) * K;

    const uint32_t sA_dst[2] = {sbase + (0 * BUF_FLOATS + a_row * LDS_K + a_col) * 4,
                                sbase + (1 * BUF_FLOATS + a_row * LDS_K + a_col) * 4};
    const uint32_t sB_dst[2] = {sbase + (0 * BUF_FLOATS + A_FLOATS + tid * LDS_K) * 4,
                                sbase + (1 * BUF_FLOATS + A_FLOATS + tid * LDS_K) * 4};

    auto prefetch = [&](int kt, int buf) {
        int k0 = kt * BK;
#pragma unroll
        for (int j = 0; j < 4; j++)
            cp_async16(sA_dst[buf] + j * 16, gA + k0 + j * 4, a_valid);
#pragma unroll
        for (int j = 0; j < 8; j++)
            cp_async16(sB_dst[buf] + j * 16, gB + k0 + j * 4, 1);
        cp_commit();
    };

    float acc[2][8][4];
#pragma unroll
    for (int mt = 0; mt < 2; mt++)
#pragma unroll
        for (int nt = 0; nt < 8; nt++)
#pragma unroll
            for (int v = 0; v < 4; v++) acc[mt][nt][v] = 0.f;

    const int nk = K / BK;
    prefetch(0, 0);
    int buf = 0;
    for (int kt = 0; kt < nk; kt++) {
        cp_wait0();
        __syncthreads();
        if (kt + 1 < nk) prefetch(kt + 1, buf ^ 1);

        const float* wA = sA[buf] + (warp_m * 32) * LDS_K;
        const float* wB = sB[buf] + (warp_n * 64) * LDS_K;
#pragma unroll
        for (int half = 0; half < 2; half++) {
            // vector fragment loads (k-permuted layout -> contiguous float4)
            float av[2][2][4];
#pragma unroll
            for (int mt = 0; mt < 2; mt++) {
                *reinterpret_cast<float4*>(av[mt][0]) =
                    *reinterpret_cast<const float4*>(wA + (mt * 16 + r) * LDS_K + c * 8 + half * 4);
                *reinterpret_cast<float4*>(av[mt][1]) =
                    *reinterpret_cast<const float4*>(wA + (mt * 16 + 8 + r) * LDS_K + c * 8 + half * 4);
            }
            float bv[8][4];
#pragma unroll
            for (int nt = 0; nt < 8; nt++)
                *reinterpret_cast<float4*>(bv[nt]) =
                    *reinterpret_cast<const float4*>(wB + (nt * 8 + r) * LDS_K + c * 8 + half * 4);
#pragma unroll
            for (int s = 0; s < 2; s++) {
#pragma unroll
                for (int mt = 0; mt < 2; mt++)
#pragma unroll
                    for (int nt = 0; nt < 8; nt++) {
                        float* d = acc[mt][nt];
                        asm volatile(
                            "mma.sync.aligned.m16n8k8.row.col.f32.tf32.tf32.f32 "
                            "{%0,%1,%2,%3}, {%4,%5,%6,%7}, {%8,%9}, {%0,%1,%2,%3};"
                            : "+f"(d[0]), "+f"(d[1]), "+f"(d[2]), "+f"(d[3])
                            : "r"(__float_as_uint(av[mt][0][2 * s])),
                              "r"(__float_as_uint(av[mt][1][2 * s])),
                              "r"(__float_as_uint(av[mt][0][2 * s + 1])),
                              "r"(__float_as_uint(av[mt][1][2 * s + 1])),
                              "r"(__float_as_uint(bv[nt][2 * s])),
                              "r"(__float_as_uint(bv[nt][2 * s + 1])));
                    }
            }
        }
        __syncthreads();
        buf ^= 1;
    }

    // ---- epilogue ----
#pragma unroll
    for (int mt = 0; mt < 2; mt++) {
#pragma unroll
        for (int half = 0; half < 2; half++) {
            int row = bm + warp_m * 32 + mt * 16 + half * 8 + r;
            if (row >= M) continue;
            float* op = out + (size_t)row * DA;
            const float* rp = (mode == 1) ? res + (size_t)row * DA : nullptr;
#pragma unroll
            for (int nt = 0; nt < 8; nt++) {
                int col = bn + warp_n * 64 + nt * 8 + c * 2;   // logical, even
                int pc = kperm(col);                           // permuted pos (pc+8 = col+1)
                float v0 = silu(acc[mt][nt][half * 2 + 0]);
                float v1 = silu(acc[mt][nt][half * 2 + 1]);
                if (mode == 1) {
                    // res is stored k-permuted
                    v0 = (rp[pc] + v0) * INV_SQRT2;
                    v1 = (rp[pc + 8] + v1) * INV_SQRT2;
                }
                if (perm_out) {
                    op[pc]     = tf32_rna(v0);
                    op[pc + 8] = tf32_rna(v1);
                } else {
                    *reinterpret_cast<float2*>(op + col) = make_float2(v0, v1);
                }
            }
        }
    }
}

// ---------------- launch ----------------
extern "C" void kernel_launch(void* const* d_in, const int* in_sizes, int n_in,
                              void* d_out, int out_size) {
    // inputs: 0:h (unused), 1:m, 2:basis_rad, 3:idx_atom, 4:W_rbf, 5:W_in, 6:res_W1, 7:res_W2
    const float* m    = (const float*)d_in[1];
    const float* br   = (const float*)d_in[2];
    const int*   idx  = (const int*)d_in[3];
    const float* Wrbf = (const float*)d_in[4];
    const float* Win  = (const float*)d_in[5];
    const float* W1   = (const float*)d_in[6];
    const float* W2   = (const float*)d_in[7];
    float* out = (float*)d_out;

    int A  = in_sizes[0] / DA;           // 20000
    int E  = in_sizes[1] / DE;           // 250000
    int nh = in_sizes[6] / (DA * DA);    // 3
    if (A > NATOMS) A = NATOMS;
    if (E > NEDGES) E = NEDGES;

    float *xbig, *xa, *ya, *wt;
    cudaGetSymbolAddress((void**)&xbig, g_xbig);
    cudaGetSymbolAddress((void**)&xa, g_xa);
    cudaGetSymbolAddress((void**)&ya, g_ya);
    cudaGetSymbolAddress((void**)&wt, g_wt);

    static bool attr_set = false;
    if (!attr_set) {
        cudaFuncSetAttribute(gemm_mma_kernel,
                             cudaFuncAttributeMaxDynamicSharedMemorySize, GEMM_SMEM);
        attr_set = true;
    }

    // counting sort of edges by atom (g_counts zeroed at load / by scan each pass)
    hist_kernel<<<(E + 255) / 256, 256>>>(idx, E);
    scan_kernel<<<1, 1024>>>(A, E);
    scatter_kernel<<<(E + 255) / 256, 256>>>(idx, E);

    // edge aggregation fused with rbf projection (writes xbig tf32+permuted)
    aggregate_kernel<<<1184, 128>>>(m, br, Wrbf, A);

    // all weight transposes in one launch
    transpose_all_kernel<<<592, 256>>>(Win, W1, W2, wt, nh);

    float* wt0 = wt;  // W_in^T [256, 512]
    dim3 grid((A + 63) / 64, DA / 128);
    // x = silu(xbig @ W_in)
    gemm_mma_kernel<<<grid, 128, GEMM_SMEM>>>(xbig, wt0, nullptr, xa, A, DE, 0, 1);

    // residual layers
    for (int i = 0; i < nh; i++) {
        float* w1t = wt + DA * DE + (size_t)(2 * i) * DA * DA;
        float* w2t = wt + DA * DE + (size_t)(2 * i + 1) * DA * DA;
        gemm_mma_kernel<<<grid, 128, GEMM_SMEM>>>(xa, w1t, nullptr, ya, A, DA, 0, 1);
        float* dst = (i == nh - 1) ? out : xa;
        int po = (i == nh - 1) ? 0 : 1;
        gemm_mma_kernel<<<grid, 128, GEMM_SMEM>>>(ya, w2t, xa, dst, A, DA, 1, po);
    }
}

// round 5
// speedup vs baseline: 1.9922x; 1.1240x over previous
#include <cuda_runtime.h>
#include <cstdint>
#include <math.h>

// Problem dims (fixed for this dataset)
#define NATOMS 20000
#define NEDGES 250000
#define DE 512
#define DA 256
#define DR 16

#define INV_SQRT2 0.70710678118654752440f

// K-permutation within each 32-element block: k' = (k%4)*8 + (k/4)%8
__host__ __device__ __forceinline__ int kperm(int k) {
    return (k & ~31) | ((k & 3) * 8) | ((k & 31) >> 2);
}

// ---------------- scratch (device globals; no allocs allowed) ----------------
__device__ int   g_counts[NATOMS];          // zero at load; scan re-zeroes each pass
__device__ int   g_offsets[NATOMS + 1];
__device__ int   g_cursor[NATOMS];
__device__ int   g_sorted[NEDGES];
__device__ float g_xbig[(size_t)NATOMS * DE];   // aggregated [A, De]; later tf32+k-permuted in place
__device__ float g_xa[(size_t)NATOMS * DA];     // atom features (tf32, k-permuted)
__device__ float g_ya[(size_t)NATOMS * DA];     // MLP intermediate (tf32, k-permuted)
// transposed+tf32-rounded+k-permuted weights: W_in^T [256,512] then 3x(W1^T,W2^T) [256,256]
__device__ float g_wt[DA * DE + 6 * DA * DA];

// ---------------- helpers ----------------
__device__ __forceinline__ uint32_t smem_u32(const void* p) {
    uint32_t a;
    asm("{ .reg .u64 t; cvta.to.shared.u64 t, %1; cvt.u32.u64 %0, t; }" : "=r"(a) : "l"(p));
    return a;
}
__device__ __forceinline__ float tf32_rna(float x) {
    float y;
    asm("cvt.rna.tf32.f32 %0, %1;" : "=f"(y) : "f"(x));
    return y;
}
__device__ __forceinline__ float silu(float x) { return x / (1.0f + __expf(-x)); }

__device__ __forceinline__ void cp_async16(uint32_t dst, const void* src, int pred) {
    asm volatile("cp.async.cg.shared.global [%0], [%1], 16, %2;"
                 :: "r"(dst), "l"(src), "r"(pred ? 16 : 0) : "memory");
}
__device__ __forceinline__ void cp_commit() {
    asm volatile("cp.async.commit_group;" ::: "memory");
}
__device__ __forceinline__ void cp_wait0() {
    asm volatile("cp.async.wait_group 0;" ::: "memory");
}

// ---------------- counting sort of edges by atom ----------------
// hist also zero-fills g_xbig (needed by the boundary atomics in aggregate)
__global__ void hist_kernel(const int* __restrict__ idx, int E, int A) {
    int i = blockIdx.x * blockDim.x + threadIdx.x;
    if (i < E) atomicAdd(&g_counts[idx[i]], 1);
    int total4 = A * DE / 4;
    int nt = gridDim.x * blockDim.x;
    float4 z = make_float4(0.f, 0.f, 0.f, 0.f);
    for (int j = i; j < total4; j += nt)
        reinterpret_cast<float4*>(g_xbig)[j] = z;
}
// single-block scan; also re-zeroes g_counts so the next graph replay starts clean
__global__ void scan_kernel(int A, int E) {
    __shared__ int sums[1024];
    int tid = threadIdx.x;
    int per = (A + 1023) / 1024;
    int start = tid * per;
    int end = min(start + per, A);
    int s = 0;
    for (int i = start; i < end; i++) s += g_counts[i];
    sums[tid] = s;
    __syncthreads();
    for (int off = 1; off < 1024; off <<= 1) {
        int v = 0;
        if (tid >= off) v = sums[tid - off];
        __syncthreads();
        sums[tid] += v;
        __syncthreads();
    }
    int run = (tid == 0) ? 0 : sums[tid - 1];
    for (int i = start; i < end; i++) {
        g_offsets[i] = run;
        g_cursor[i]  = run;
        run += g_counts[i];
        g_counts[i] = 0;
    }
    if (tid == 0) g_offsets[A] = E;
}
__global__ void scatter_kernel(const int* __restrict__ idx, int E) {
    int i = blockIdx.x * blockDim.x + threadIdx.x;
    if (i < E) {
        int p = atomicAdd(&g_cursor[idx[i]], 1);
        g_sorted[p] = i;
    }
}

// ---------------- edge-parallel aggregation fused with rbf projection ----------------
// xbig[a, d] += m[e,d] * (sum_r basis_rad[e,r] * W_rbf[r,d])  for e in sorted order.
// Blocks own contiguous sorted-edge ranges; interior atoms flushed with plain stores,
// range-boundary atoms with atomicAdd (xbig pre-zeroed by hist_kernel).
#define AGG_TILE 64
#define AGG_BLOCKS 740

__global__ __launch_bounds__(128, 5)
void aggregate_kernel(const float* __restrict__ m,
                      const float* __restrict__ br,
                      const float* __restrict__ Wrbf,
                      const int* __restrict__ idx, int E) {
    __shared__ float s_br[AGG_TILE][16];
    __shared__ int   s_e[AGG_TILE];
    __shared__ int   s_atom[AGG_TILE];

    const int tid = threadIdx.x;
    const int c0 = tid * 4;
    float4 w[DR];
#pragma unroll
    for (int r = 0; r < DR; r++)
        w[r] = *reinterpret_cast<const float4*>(Wrbf + (size_t)r * DE + c0);

    const int epb = (E + gridDim.x - 1) / gridDim.x;
    const int j0 = blockIdx.x * epb;
    const int j1 = min(j0 + epb, E);
    if (j0 >= j1) return;

    const int first_a = idx[g_sorted[j0]];
    const int last_a  = idx[g_sorted[j1 - 1]];

    float4 acc = make_float4(0.f, 0.f, 0.f, 0.f);
    int cur_atom = -1;

    auto flush = [&](int a) {
        float* p = g_xbig + (size_t)a * DE + c0;
        if (a != first_a && a != last_a) {
            *reinterpret_cast<float4*>(p) = acc;   // interior: exclusive owner
        } else {
            atomicAdd(p + 0, acc.x);
            atomicAdd(p + 1, acc.y);
            atomicAdd(p + 2, acc.z);
            atomicAdd(p + 3, acc.w);
        }
    };

    for (int t0 = j0; t0 < j1; t0 += AGG_TILE) {
        const int n = min(AGG_TILE, j1 - t0);
        __syncthreads();
        {   // stage: 2 threads per edge; thread loads 8 floats of basis_rad row
            int el = tid >> 1;
            int half = tid & 1;
            if (el < n) {
                int e = g_sorted[t0 + el];
                if (half == 0) { s_e[el] = e; s_atom[el] = idx[e]; }
                const float* bp = br + (size_t)e * DR + half * 8;
                *reinterpret_cast<float4*>(&s_br[el][half * 8]) =
                    *reinterpret_cast<const float4*>(bp);
                *reinterpret_cast<float4*>(&s_br[el][half * 8 + 4]) =
                    *reinterpret_cast<const float4*>(bp + 4);
            }
        }
        __syncthreads();

        float4 mv = *reinterpret_cast<const float4*>(m + (size_t)s_e[0] * DE + c0);
        for (int i = 0; i < n; i++) {
            float4 mnext = mv;
            if (i + 1 < n)
                mnext = *reinterpret_cast<const float4*>(m + (size_t)s_e[i + 1] * DE + c0);

            int a = s_atom[i];
            if (a != cur_atom) {
                if (cur_atom >= 0) flush(cur_atom);
                cur_atom = a;
                acc = make_float4(0.f, 0.f, 0.f, 0.f);
            }
            float4 bs = make_float4(0.f, 0.f, 0.f, 0.f);
            const float4* bq = reinterpret_cast<const float4*>(s_br[i]);
#pragma unroll
            for (int q = 0; q < 4; q++) {
                float4 bb = bq[q];   // broadcast LDS.128
                float4 w0 = w[q * 4 + 0], w1 = w[q * 4 + 1];
                float4 w2 = w[q * 4 + 2], w3 = w[q * 4 + 3];
                bs.x = fmaf(bb.x, w0.x, bs.x); bs.y = fmaf(bb.x, w0.y, bs.y);
                bs.z = fmaf(bb.x, w0.z, bs.z); bs.w = fmaf(bb.x, w0.w, bs.w);
                bs.x = fmaf(bb.y, w1.x, bs.x); bs.y = fmaf(bb.y, w1.y, bs.y);
                bs.z = fmaf(bb.y, w1.z, bs.z); bs.w = fmaf(bb.y, w1.w, bs.w);
                bs.x = fmaf(bb.z, w2.x, bs.x); bs.y = fmaf(bb.z, w2.y, bs.y);
                bs.z = fmaf(bb.z, w2.z, bs.z); bs.w = fmaf(bb.z, w2.w, bs.w);
                bs.x = fmaf(bb.w, w3.x, bs.x); bs.y = fmaf(bb.w, w3.y, bs.y);
                bs.z = fmaf(bb.w, w3.z, bs.z); bs.w = fmaf(bb.w, w3.w, bs.w);
            }
            acc.x = fmaf(mv.x, bs.x, acc.x);
            acc.y = fmaf(mv.y, bs.y, acc.y);
            acc.z = fmaf(mv.z, bs.z, acc.z);
            acc.w = fmaf(mv.w, bs.w, acc.w);
            mv = mnext;
        }
    }
    if (cur_atom >= 0) flush(cur_atom);
}

// ---------------- fixup: tf32-round + k-permute xbig rows in place ----------------
__global__ void fixup_kernel(int A) {
    int total = A * DE / 32;
    for (int i = blockIdx.x * blockDim.x + threadIdx.x; i < total;
         i += gridDim.x * blockDim.x) {
        float* p = g_xbig + (size_t)i * 32;
        float v[32];
#pragma unroll
        for (int j = 0; j < 8; j++)
            *reinterpret_cast<float4*>(&v[j * 4]) = reinterpret_cast<float4*>(p)[j];
        float o[32];
#pragma unroll
        for (int j = 0; j < 32; j++)
            o[j] = tf32_rna(v[(j & 7) * 4 + (j >> 3)]);
#pragma unroll
        for (int j = 0; j < 8; j++)
            reinterpret_cast<float4*>(p)[j] = *reinterpret_cast<float4*>(&o[j * 4]);
    }
}

// ---------------- all-weights transpose + tf32 round + k-permute (single launch) ----------------
__global__ void transpose_all_kernel(const float* __restrict__ Win,
                                     const float* __restrict__ W1,
                                     const float* __restrict__ W2,
                                     float* __restrict__ wt, int nh) {
    int total = DE * DA + 2 * nh * DA * DA;
    for (int i = blockIdx.x * blockDim.x + threadIdx.x; i < total;
         i += gridDim.x * blockDim.x) {
        const float* src;
        float* dst;
        int K, rem;
        if (i < DE * DA) {
            src = Win; dst = wt; K = DE; rem = i;
        } else {
            int j = i - DE * DA;
            int t = j / (DA * DA);
            rem = j % (DA * DA);
            src = ((t & 1) == 0 ? W1 : W2) + (size_t)(t >> 1) * DA * DA;
            dst = wt + DE * DA + (size_t)t * DA * DA;
            K = DA;
        }
        int k = rem / DA, n = rem % DA;
        dst[(size_t)n * K + kperm(k)] = tf32_rna(src[rem]);
    }
}

// ---------------- mma.sync tf32 GEMM, tile 64x128, k-permuted operands ----------------
#define BK 32
#define LDS_K 36
#define A_FLOATS (64 * LDS_K)
#define B_FLOATS (128 * LDS_K)
#define BUF_FLOATS (A_FLOATS + B_FLOATS)
#define GEMM_SMEM (2 * BUF_FLOATS * 4)   // 55296 B

__global__ __launch_bounds__(128, 3)
void gemm_mma_kernel(const float* __restrict__ Ain, const float* __restrict__ Wt,
                     const float* __restrict__ res, float* __restrict__ out,
                     int M, int K, int mode, int perm_out) {
    extern __shared__ float smem[];
    float* sA[2] = {smem, smem + BUF_FLOATS};
    float* sB[2] = {smem + A_FLOATS, smem + BUF_FLOATS + A_FLOATS};
    const uint32_t sbase = smem_u32(smem);

    const int tid = threadIdx.x;
    const int lane = tid & 31;
    const int wid = tid >> 5;
    const int warp_m = wid & 1;
    const int warp_n = wid >> 1;
    const int bm = blockIdx.x * 64;
    const int bn = blockIdx.y * 128;
    const int r = lane >> 2;
    const int c = lane & 3;

    const int a_row = tid >> 1;
    const int a_col = (tid & 1) * 16;
    const bool a_valid = (bm + a_row) < M;
    const float* gA = Ain + (size_t)(bm + a_row) * K + a_col;
    const float* gB = Wt + (size_t)(bn + tid) * K;

    const uint32_t sA_dst[2] = {sbase + (0 * BUF_FLOATS + a_row * LDS_K + a_col) * 4,
                                sbase + (1 * BUF_FLOATS + a_row * LDS_K + a_col) * 4};
    const uint32_t sB_dst[2] = {sbase + (0 * BUF_FLOATS + A_FLOATS + tid * LDS_K) * 4,
                                sbase + (1 * BUF_FLOATS + A_FLOATS + tid * LDS_K) * 4};

    auto prefetch = [&](int kt, int buf) {
        int k0 = kt * BK;
#pragma unroll
        for (int j = 0; j < 4; j++)
            cp_async16(sA_dst[buf] + j * 16, gA + k0 + j * 4, a_valid);
#pragma unroll
        for (int j = 0; j < 8; j++)
            cp_async16(sB_dst[buf] + j * 16, gB + k0 + j * 4, 1);
        cp_commit();
    };

    float acc[2][8][4];
#pragma unroll
    for (int mt = 0; mt < 2; mt++)
#pragma unroll
        for (int nt = 0; nt < 8; nt++)
#pragma unroll
            for (int v = 0; v < 4; v++) acc[mt][nt][v] = 0.f;

    const int nk = K / BK;
    prefetch(0, 0);
    int buf = 0;
    for (int kt = 0; kt < nk; kt++) {
        cp_wait0();
        __syncthreads();
        if (kt + 1 < nk) prefetch(kt + 1, buf ^ 1);

        const float* wA = sA[buf] + (warp_m * 32) * LDS_K;
        const float* wB = sB[buf] + (warp_n * 64) * LDS_K;
#pragma unroll
        for (int half = 0; half < 2; half++) {
            float av[2][2][4];
#pragma unroll
            for (int mt = 0; mt < 2; mt++) {
                *reinterpret_cast<float4*>(av[mt][0]) =
                    *reinterpret_cast<const float4*>(wA + (mt * 16 + r) * LDS_K + c * 8 + half * 4);
                *reinterpret_cast<float4*>(av[mt][1]) =
                    *reinterpret_cast<const float4*>(wA + (mt * 16 + 8 + r) * LDS_K + c * 8 + half * 4);
            }
            float bv[8][4];
#pragma unroll
            for (int nt = 0; nt < 8; nt++)
                *reinterpret_cast<float4*>(bv[nt]) =
                    *reinterpret_cast<const float4*>(wB + (nt * 8 + r) * LDS_K + c * 8 + half * 4);
#pragma unroll
            for (int s = 0; s < 2; s++) {
#pragma unroll
                for (int mt = 0; mt < 2; mt++)
#pragma unroll
                    for (int nt = 0; nt < 8; nt++) {
                        float* d = acc[mt][nt];
                        asm volatile(
                            "mma.sync.aligned.m16n8k8.row.col.f32.tf32.tf32.f32 "
                            "{%0,%1,%2,%3}, {%4,%5,%6,%7}, {%8,%9}, {%0,%1,%2,%3};"
                            : "+f"(d[0]), "+f"(d[1]), "+f"(d[2]), "+f"(d[3])
                            : "r"(__float_as_uint(av[mt][0][2 * s])),
                              "r"(__float_as_uint(av[mt][1][2 * s])),
                              "r"(__float_as_uint(av[mt][0][2 * s + 1])),
                              "r"(__float_as_uint(av[mt][1][2 * s + 1])),
                              "r"(__float_as_uint(bv[nt][2 * s])),
                              "r"(__float_as_uint(bv[nt][2 * s + 1])));
                    }
            }
        }
        __syncthreads();
        buf ^= 1;
    }

#pragma unroll
    for (int mt = 0; mt < 2; mt++) {
#pragma unroll
        for (int half = 0; half < 2; half++) {
            int row = bm + warp_m * 32 + mt * 16 + half * 8 + r;
            if (row >= M) continue;
            float* op = out + (size_t)row * DA;
            const float* rp = (mode == 1) ? res + (size_t)row * DA : nullptr;
#pragma unroll
            for (int nt = 0; nt < 8; nt++) {
                int col = bn + warp_n * 64 + nt * 8 + c * 2;
                int pc = kperm(col);
                float v0 = silu(acc[mt][nt][half * 2 + 0]);
                float v1 = silu(acc[mt][nt][half * 2 + 1]);
                if (mode == 1) {
                    v0 = (rp[pc] + v0) * INV_SQRT2;
                    v1 = (rp[pc + 8] + v1) * INV_SQRT2;
                }
                if (perm_out) {
                    op[pc]     = tf32_rna(v0);
                    op[pc + 8] = tf32_rna(v1);
                } else {
                    *reinterpret_cast<float2*>(op + col) = make_float2(v0, v1);
                }
            }
        }
    }
}

// ---------------- launch ----------------
extern "C" void kernel_launch(void* const* d_in, const int* in_sizes, int n_in,
                              void* d_out, int out_size) {
    // inputs: 0:h (unused), 1:m, 2:basis_rad, 3:idx_atom, 4:W_rbf, 5:W_in, 6:res_W1, 7:res_W2
    const float* m    = (const float*)d_in[1];
    const float* br   = (const float*)d_in[2];
    const int*   idx  = (const int*)d_in[3];
    const float* Wrbf = (const float*)d_in[4];
    const float* Win  = (const float*)d_in[5];
    const float* W1   = (const float*)d_in[6];
    const float* W2   = (const float*)d_in[7];
    float* out = (float*)d_out;

    int A  = in_sizes[0] / DA;           // 20000
    int E  = in_sizes[1] / DE;           // 250000
    int nh = in_sizes[6] / (DA * DA);    // 3
    if (A > NATOMS) A = NATOMS;
    if (E > NEDGES) E = NEDGES;

    float *xbig, *xa, *ya, *wt;
    cudaGetSymbolAddress((void**)&xbig, g_xbig);
    cudaGetSymbolAddress((void**)&xa, g_xa);
    cudaGetSymbolAddress((void**)&ya, g_ya);
    cudaGetSymbolAddress((void**)&wt, g_wt);

    static bool attr_set = false;
    if (!attr_set) {
        cudaFuncSetAttribute(gemm_mma_kernel,
                             cudaFuncAttributeMaxDynamicSharedMemorySize, GEMM_SMEM);
        attr_set = true;
    }

    // counting sort (hist also zero-fills xbig for the aggregation atomics)
    hist_kernel<<<(E + 255) / 256, 256>>>(idx, E, A);
    scan_kernel<<<1, 1024>>>(A, E);
    scatter_kernel<<<(E + 255) / 256, 256>>>(idx, E);

    // edge-parallel aggregation (launch #4 locally -> ncu capture slot)
    aggregate_kernel<<<AGG_BLOCKS, 128>>>(m, br, Wrbf, idx, E);

    // round+permute xbig in place
    fixup_kernel<<<640, 256>>>(A);

    // all weight transposes in one launch
    transpose_all_kernel<<<592, 256>>>(Win, W1, W2, wt, nh);

    float* wt0 = wt;  // W_in^T [256, 512]
    dim3 grid((A + 63) / 64, DA / 128);
    // x = silu(xbig @ W_in)
    gemm_mma_kernel<<<grid, 128, GEMM_SMEM>>>(xbig, wt0, nullptr, xa, A, DE, 0, 1);

    // residual layers
    for (int i = 0; i < nh; i++) {
        float* w1t = wt + DA * DE + (size_t)(2 * i) * DA * DA;
        float* w2t = wt + DA * DE + (size_t)(2 * i + 1) * DA * DA;
        gemm_mma_kernel<<<grid, 128, GEMM_SMEM>>>(xa, w1t, nullptr, ya, A, DA, 0, 1);
        float* dst = (i == nh - 1) ? out : xa;
        int po = (i == nh - 1) ? 0 : 1;
        gemm_mma_kernel<<<grid, 128, GEMM_SMEM>>>(ya, w2t, xa, dst, A, DA, 1, po);
    }
}